// round 5
// baseline (speedup 1.0000x reference)
#include <cuda_runtime.h>

// Pyramid Givens circuit, n = m = 512, B = 256.
// Layer t in [0,1021): gates (i,i+1) for i ≡ t (mod 2), 0 <= i <= min(t, 1020-t).
// theta index: q=(t+i)/2, tidx = q(q+1)/2 + q - i.  Gate: a'=c*a+s*b ; b'=c*b-s*a.
//
// 2 warps per row: h=0 owns wires 0..255 (+halo 256..271), h=1 owns 256..511
// (+halo 240..255). Lane L owns wires W..W+7 (W=256h+8L), packed
// P[k]=(v_{W+k}, v_{W+k+4}). Halo wire haloBase_h + λ lives in lane λ (λ<16).
// Halo evolves in-warp (shuffles); staleness invades 1 wire/layer from the far
// edge; a 16-wire halo with 12-layer exchange period keeps owned wires exact.
// Exchange = smem + one named barrier per 12 layers. Triangle: halo + h=1 work
// only needed for t in [240, 792) = exchange periods 20..65 exactly.

#define N_WIRES   512
#define CHUNK_L   4                    // layers per cp.async chunk (2 stages)
#define NCHUNK    258                  // 1032 layers (>=1021; tail identity)
#define T_PAD     (NCHUNK * CHUNK_L)   // 1032
#define ROT_OFF   0                    // 128 double2 = 2048 B
#define LEFT_OFF  2048                 // 64 float2  =  512 B
#define HALO_OFF  2560                 // 32 float2  =  256 B
#define LAYER_B   2816
#define CHUNK_B   (CHUNK_L * LAYER_B)  // 11264

typedef unsigned long long ull;

__device__ __align__(16) char g_tab[(size_t)T_PAD * LAYER_B];   // ~2.9 MB

__device__ __forceinline__ float2 cs_of(const float* __restrict__ th, int t, int i) {
    if (t <= 1020 && i >= 0 && i <= t && i <= 1020 - t && (((i ^ t) & 1) == 0)) {
        int q = (t + i) >> 1;
        int tidx = (q * (q + 1)) / 2 + q - i;
        float s, c;
        sincosf(th[tidx], &s, &c);
        return make_float2(c, s);
    }
    return make_float2(1.0f, 0.0f);
}

__global__ void build_cs_kernel(const float* __restrict__ thetas) {
    int t    = blockIdx.x;            // 0..T_PAD-1 (t > 1020 -> identity)
    int h    = threadIdx.x >> 6;      // 0,1
    int r    = (threadIdx.x >> 5) & 1;
    int lane = threadIdx.x & 31;
    int w    = 256 * h + 8 * lane;
    char* base = g_tab + (size_t)t * LAYER_B;

    // rot entries: even t r: gates (w+2r, w+2r+4 offsets) as in prior rounds
    int ilo, ihi;
    if ((t & 1) == 0) { ilo = w + 2 * r;     ihi = ilo + 4; }
    else              { ilo = w + 2 * r + 1; ihi = ilo + 4; }
    float2 a = cs_of(thetas, t, ilo);
    float2 b = cs_of(thetas, t, ihi);
    float2* dst = reinterpret_cast<float2*>(base + ROT_OFF + ((h * 2 + r) * 32 + lane) * 16);
    dst[0] = make_float2(a.x, b.x);   // c2
    dst[1] = make_float2(a.y, b.y);   // s2

    if (r == 0) {  // left-gate (w-1, w)
        float2 lf = cs_of(thetas, t, w - 1);
        *reinterpret_cast<float2*>(base + LEFT_OFF + (h * 32 + lane) * 8) = lf;
    }
    if (r == 1 && lane < 16) {  // halo entry: H' = A*H + B*partner
        int u = (h == 0 ? 256 : 240) + lane;
        float A, B;
        if (((u ^ t) & 1) == 0) {             // left member, gate (u, u+1)
            bool ext = (h == 0 && lane == 15);  // (271,272): partner unknown -> stale
            float2 g = cs_of(thetas, t, u);
            A = ext ? 1.0f : g.x;  B = ext ? 0.0f : g.y;
        } else {                               // right member, gate (u-1, u)
            bool ext = (h == 1 && lane == 0);   // (239,240): partner unknown -> stale
            float2 g = cs_of(thetas, t, u - 1);
            A = ext ? 1.0f : g.x;  B = ext ? 0.0f : -g.y;
        }
        *reinterpret_cast<float2*>(base + HALO_OFF + (h * 16 + lane) * 8) = make_float2(A, B);
    }
}

// ---- f32x2 helpers ----
__device__ __forceinline__ ull mul2(ull a, ull b) {
    ull d; asm("mul.rn.f32x2 %0, %1, %2;" : "=l"(d) : "l"(a), "l"(b)); return d;
}
__device__ __forceinline__ ull fma2(ull a, ull b, ull c) {
    ull d; asm("fma.rn.f32x2 %0, %1, %2, %3;" : "=l"(d) : "l"(a), "l"(b), "l"(c)); return d;
}
__device__ __forceinline__ float lo_f(ull p) {
    float lo, hi; asm("mov.b64 {%0, %1}, %2;" : "=f"(lo), "=f"(hi) : "l"(p)); return lo;
}
__device__ __forceinline__ float hi_f(ull p) {
    float lo, hi; asm("mov.b64 {%0, %1}, %2;" : "=f"(lo), "=f"(hi) : "l"(p)); return hi;
}
__device__ __forceinline__ ull pk(float lo, float hi) {
    ull d; asm("mov.b64 %0, {%1, %2};" : "=l"(d) : "f"(lo), "f"(hi)); return d;
}

#define SGNMASK 0x8000000080000000ULL
#define FULLM   0xffffffffu

__device__ __forceinline__ void rotp(ull& a, ull& b, double2 cs) {
    ull c2 = __double_as_longlong(cs.x);
    ull s2 = __double_as_longlong(cs.y);
    ull t1 = mul2(s2, b);
    ull na = fma2(c2, a, t1);
    ull t2 = mul2(s2, a) ^ SGNMASK;
    b = fma2(c2, b, t2);
    a = na;
}

__device__ __forceinline__ void cp16(char* dst_smem, const char* src) {
    unsigned d = (unsigned)__cvta_generic_to_shared(dst_smem);
    asm volatile("cp.async.cg.shared.global [%0], [%1], 16;" :: "r"(d), "l"(src));
}
__device__ __forceinline__ void cp_commit() { asm volatile("cp.async.commit_group;"); }
__device__ __forceinline__ void cp_wait1()  { asm volatile("cp.async.wait_group 1;" ::: "memory"); }
__device__ __forceinline__ void bar_pair(int id) {
    asm volatile("bar.sync %0, 64;" :: "r"(id) : "memory");
}

// block = 128 threads: wid 0,1 = row 2b halves 0,1; wid 2,3 = row 2b+1.
__global__ void __launch_bounds__(128, 1) apply_kernel(
    const float* __restrict__ x,
    const float* __restrict__ bias,
    float* __restrict__ out)
{
    __shared__ __align__(16) char sbuf[3][CHUNK_B];   // 33792 B
    __shared__ float seamA[2][16];   // h1 owned wires 256..271 -> h0 halo
    __shared__ float seamB[2][16];   // h0 owned wires 240..255 -> h1 halo

    const int tid  = threadIdx.x;
    const int wid  = tid >> 5;
    const int lane = tid & 31;
    const int rp   = wid >> 1;
    const int h    = wid & 1;
    const int row  = blockIdx.x * 2 + rp;
    const int w    = 256 * h;

    ull P[4];
    {
        const float4* xr = reinterpret_cast<const float4*>(x + (size_t)row * N_WIRES + w) + lane * 2;
        float4 f0 = xr[0], f1 = xr[1];
        P[0] = pk(f0.x, f1.x);
        P[1] = pk(f0.y, f1.y);
        P[2] = pk(f0.z, f1.z);
        P[3] = pk(f0.w, f1.w);
    }
    float H = 0.0f;   // halo wire (haloBase + lane), lanes 0..15

    // prologue: chunks 0,1
    #pragma unroll 1
    for (int pc = 0; pc < 2; ++pc) {
        const char* src = g_tab + (size_t)pc * CHUNK_B;
        for (int off = tid * 16; off < CHUNK_B; off += 128 * 16)
            cp16(&sbuf[pc][off], src + off);
        cp_commit();
    }

    const int rotOff  = ROT_OFF  + ((h * 2) * 32 + lane) * 16;  // r=0; r=1 at +512
    const int leftOff = LEFT_OFF + (h * 32 + lane) * 8;
    const int haloOff = HALO_OFF + (h * 16 + (lane & 15)) * 8;

    int rb = 0, ib = 2;
    #pragma unroll 1
    for (int c = 0; c < NCHUNK; ++c) {
        cp_wait1();
        __syncthreads();

        if (c + 2 < NCHUNK) {
            const char* src = g_tab + (size_t)(c + 2) * CHUNK_B;
            for (int off = tid * 16; off < CHUNK_B; off += 128 * 16)
                cp16(&sbuf[ib][off], src + off);
        }
        cp_commit();

        // halo exchange every 3 chunks (12 layers), incl. c==0 (halo init)
        if (c % 3 == 0) {
            if (h == 1 && lane < 2) {          // wires 256..271
                #pragma unroll
                for (int k = 0; k < 4; ++k) {
                    seamA[rp][lane * 8 + k]     = lo_f(P[k]);
                    seamA[rp][lane * 8 + 4 + k] = hi_f(P[k]);
                }
            }
            if (h == 0 && lane >= 30) {        // wires 240..255
                #pragma unroll
                for (int k = 0; k < 4; ++k) {
                    seamB[rp][(lane - 30) * 8 + k]     = lo_f(P[k]);
                    seamB[rp][(lane - 30) * 8 + 4 + k] = hi_f(P[k]);
                }
            }
            bar_pair(rp + 1);
            if (lane < 16) H = (h == 0) ? seamA[rp][lane] : seamB[rp][lane];
        }

        const char* cb = sbuf[rb];
        #pragma unroll
        for (int sl = 0; sl < 2; ++sl) {
            const int t0 = c * CHUNK_L + 2 * sl;
            const bool hw  = (t0 >= 240 && t0 < 792);   // halo window (periods 20..65)
            const bool act = (h == 0) || hw;            // h1 triangle skip

            if (act) {
                const char* le = cb + (2 * sl) * LAYER_B;
                const char* lo = le + LAYER_B;
                double2 E0 = *reinterpret_cast<const double2*>(le + rotOff);
                double2 E1 = *reinterpret_cast<const double2*>(le + rotOff + 512);
                double2 O0 = *reinterpret_cast<const double2*>(lo + rotOff);
                double2 O1 = *reinterpret_cast<const double2*>(lo + rotOff + 512);
                float2  LF = *reinterpret_cast<const float2*>(lo + leftOff);

                // ---- owned even layer ----
                rotp(P[0], P[1], E0);
                rotp(P[2], P[3], E1);

                // ---- halo even layer ----
                if (hw) {
                    float2 hc = *reinterpret_cast<const float2*>(le + haloOff);
                    float p = __shfl_xor_sync(FULLM, H, 1);
                    H = fmaf(hc.x, H, hc.y * p);
                }
                // post-even halo boundary values for owned odd layer
                float hv0  = __shfl_sync(FULLM, H, 0);    // wire 256 (h0) / 240 (h1)
                float hv15 = __shfl_sync(FULLM, H, 15);   // wire 271 (h0) / 255 (h1)

                // ---- halo odd layer (uses owned post-even seam values) ----
                if (hw) {
                    float2 hc = *reinterpret_cast<const float2*>(lo + haloOff);
                    float val = (h == 0) ? hi_f(P[3]) : lo_f(P[0]);   // wire 255 / 256
                    float ext = __shfl_sync(FULLM, val, (h == 0) ? 31 : 0);
                    int pidx = ((((lane & 15) + 1) ^ 1) - 1) & 31;
                    float p = __shfl_sync(FULLM, H, pidx);
                    if (h == 0) { if (lane == 0)  p = ext; }
                    else        { if (lane == 15) p = ext; }
                    H = fmaf(hc.x, H, hc.y * p);
                }

                // ---- owned odd layer ----
                float vnext = __shfl_down_sync(FULLM, lo_f(P[0]), 1);
                if (lane == 31) vnext = (h == 0) ? hv0 : 0.0f;   // wire 256 post-even
                float lv = __shfl_up_sync(FULLM, hi_f(P[3]), 1);
                if (h == 1 && lane == 0) lv = hv15;              // wire 255 post-even

                rotp(P[1], P[2], O0);
                ull Q = pk(hi_f(P[0]), vnext);
                rotp(P[3], Q, O1);
                float nv0 = fmaf(LF.x, lo_f(P[0]), -(LF.y * lv));
                P[0] = pk(nv0, lo_f(Q));
            }
        }

        rb = (rb == 2) ? 0 : rb + 1;
        ib = (ib == 2) ? 0 : ib + 1;
    }

    // store + bias
    {
        const float4* bb   = reinterpret_cast<const float4*>(bias + w) + lane * 2;
        float4*       outr = reinterpret_cast<float4*>(out + (size_t)row * N_WIRES + w) + lane * 2;
        float4 b0 = bb[0], b1 = bb[1];
        float4 o0, o1;
        o0.x = lo_f(P[0]) + b0.x; o0.y = lo_f(P[1]) + b0.y;
        o0.z = lo_f(P[2]) + b0.z; o0.w = lo_f(P[3]) + b0.w;
        o1.x = hi_f(P[0]) + b1.x; o1.y = hi_f(P[1]) + b1.y;
        o1.z = hi_f(P[2]) + b1.z; o1.w = hi_f(P[3]) + b1.w;
        outr[0] = o0; outr[1] = o1;
    }
}

extern "C" void kernel_launch(void* const* d_in, const int* in_sizes, int n_in,
                              void* d_out, int out_size) {
    const float* x      = (const float*)d_in[0];
    const float* thetas = (const float*)d_in[1];
    const float* bias   = (const float*)d_in[2];
    float* out = (float*)d_out;

    build_cs_kernel<<<T_PAD, 128>>>(thetas);

    int B = in_sizes[0] / N_WIRES;   // 256
    apply_kernel<<<B / 2, 128>>>(x, bias, out);
}

// round 6
// speedup vs baseline: 2.2660x; 2.2660x over previous
#include <cuda_runtime.h>

// Pyramid Givens circuit, n = m = 512, B = 256.
// Layer t in [0,1021): gates (i,i+1) for i ≡ t (mod 2), 0 <= i <= min(t, 1020-t).
// theta index: q=(t+i)/2, tidx = q(q+1)/2 + q - i.
// Gate: a' = c*a + s*b ; b' = c*b - s*a.

#define N_WIRES   512
#define CHUNK_L   6                    // layers per bulk-copy chunk (3 two-layer stages)
#define NCHUNK    172                  // 172 * 6 = 1032 layers (>= 1021; tail identity)
#define T_PAD     (NCHUNK * CHUNK_L)   // 1032
#define LAYER_B   2304                 // 4*32*16 (rot double2) + 32*8 (left float2)
#define CHUNK_B   (CHUNK_L * LAYER_B)  // 13824
#define LEFT_OFF  2048

typedef unsigned long long ull;

// Per layer t (stride LAYER_B bytes):
//   [0,2048): rot cs, entry (r,lane) at r*512 + lane*16, as double2 {c2,s2} (f32x2 payloads)
//     even t, r=0..3: rot (P_2r,P_2r+1): lo gate wire 16L+2r, hi gate 16L+2r+8
//     odd t,  r=0..2: rot (P_2r+1,P_2r+2): lo gate 16L+2r+1, hi gate 16L+2r+9
//     odd t,  r=3:    boundary rot (P7,Q): lo gate 16L+7, hi gate 16L+15
//   [2048,2304): left-gate float2 (c,s) per lane: gate at wire 16L-1 (lane 0 -> identity)
// Inactive gates stored as identity (1,0).
__device__ __align__(128) char g_tab[(size_t)T_PAD * LAYER_B];   // ~2.3 MB

__device__ __forceinline__ float2 cs_of(const float* __restrict__ th, int t, int i) {
    if (t <= 1020 && i >= 0 && i <= t && i <= 1020 - t && (((i ^ t) & 1) == 0)) {
        int q = (t + i) >> 1;
        int tidx = (q * (q + 1)) / 2 + q - i;
        float s, c;
        sincosf(th[tidx], &s, &c);
        return make_float2(c, s);
    }
    return make_float2(1.0f, 0.0f);
}

__global__ void build_cs_kernel(const float* __restrict__ thetas) {
    int t    = blockIdx.x;          // 0..T_PAD-1 (t > 1020 -> identity)
    int r    = threadIdx.x >> 5;    // 0..3
    int lane = threadIdx.x & 31;
    int base = 16 * lane;
    int ilo, ihi;
    if ((t & 1) == 0)      { ilo = base + 2 * r;     ihi = ilo + 8; }
    else if (r < 3)        { ilo = base + 2 * r + 1; ihi = ilo + 8; }
    else                   { ilo = base + 7;         ihi = base + 15; }
    float2 a = cs_of(thetas, t, ilo);
    float2 b = cs_of(thetas, t, ihi);
    float2* dst = reinterpret_cast<float2*>(g_tab + (size_t)t * LAYER_B + r * 512 + lane * 16);
    dst[0] = make_float2(a.x, b.x);   // c2 = (c_lo, c_hi)
    dst[1] = make_float2(a.y, b.y);   // s2 = (s_lo, s_hi)
    if (r == 3) {
        float2 lf = (lane == 0) ? make_float2(1.0f, 0.0f) : cs_of(thetas, t, base - 1);
        *reinterpret_cast<float2*>(g_tab + (size_t)t * LAYER_B + LEFT_OFF + lane * 8) = lf;
    }
}

// ---- f32x2 helpers ----
__device__ __forceinline__ ull mul2(ull a, ull b) {
    ull d; asm("mul.rn.f32x2 %0, %1, %2;" : "=l"(d) : "l"(a), "l"(b)); return d;
}
__device__ __forceinline__ ull fma2(ull a, ull b, ull c) {
    ull d; asm("fma.rn.f32x2 %0, %1, %2, %3;" : "=l"(d) : "l"(a), "l"(b), "l"(c)); return d;
}
__device__ __forceinline__ float lo_f(ull p) {
    float lo, hi; asm("mov.b64 {%0, %1}, %2;" : "=f"(lo), "=f"(hi) : "l"(p)); return lo;
}
__device__ __forceinline__ float hi_f(ull p) {
    float lo, hi; asm("mov.b64 {%0, %1}, %2;" : "=f"(lo), "=f"(hi) : "l"(p)); return hi;
}
__device__ __forceinline__ ull pk(float lo, float hi) {
    ull d; asm("mov.b64 %0, {%1, %2};" : "=l"(d) : "f"(lo), "f"(hi)); return d;
}

#define SGNMASK 0x8000000080000000ULL

// Packed Givens: a' = c*a + s*b ; b' = c*b - s*a
__device__ __forceinline__ void rotp(ull& a, ull& b, double2 cs) {
    ull c2 = __double_as_longlong(cs.x);
    ull s2 = __double_as_longlong(cs.y);
    ull t1 = mul2(s2, b);
    ull na = fma2(c2, a, t1);
    ull t2 = mul2(s2, a) ^ SGNMASK;      // -s*a
    b = fma2(c2, b, t2);
    a = na;
}

// ---- bulk-copy / mbarrier helpers ----
__device__ __forceinline__ unsigned s2u(const void* p) {
    return (unsigned)__cvta_generic_to_shared(p);
}
__device__ __forceinline__ void mbar_init(unsigned mbar, unsigned cnt) {
    asm volatile("mbarrier.init.shared.b64 [%0], %1;" :: "r"(mbar), "r"(cnt) : "memory");
}
__device__ __forceinline__ void mbar_expect_tx(unsigned mbar, unsigned bytes) {
    asm volatile("mbarrier.arrive.expect_tx.shared.b64 _, [%0], %1;"
                 :: "r"(mbar), "r"(bytes) : "memory");
}
__device__ __forceinline__ void bulk_g2s(unsigned dst, const void* src, unsigned bytes,
                                         unsigned mbar) {
    asm volatile("cp.async.bulk.shared::cluster.global.mbarrier::complete_tx::bytes "
                 "[%0], [%1], %2, [%3];"
                 :: "r"(dst), "l"(src), "r"(bytes), "r"(mbar) : "memory");
}
__device__ __forceinline__ void mbar_wait(unsigned mbar, unsigned parity) {
    unsigned done;
    asm volatile(
        "{\n\t.reg .pred p;\n\t"
        "mbarrier.try_wait.parity.acquire.cta.shared::cta.b64 p, [%1], %2;\n\t"
        "selp.b32 %0, 1, 0, p;\n\t}"
        : "=r"(done) : "r"(mbar), "r"(parity) : "memory");
    if (!done) {
        asm volatile(
            "{\n\t.reg .pred P1;\n\t"
            "WL_%=:\n\t"
            "mbarrier.try_wait.parity.acquire.cta.shared::cta.b64 P1, [%0], %1, 0x989680;\n\t"
            "@P1 bra.uni WD_%=;\n\t"
            "bra.uni WL_%=;\n\t"
            "WD_%=:\n\t}"
            :: "r"(mbar), "r"(parity) : "memory");
    }
}
__device__ __forceinline__ void fence_async_shared() {
    asm volatile("fence.proxy.async.shared::cta;" ::: "memory");
}

// One warp per batch row, 2 warps per CTA. cs table streamed global->smem via
// single-thread cp.async.bulk (3 buffers, 3 chunks in flight), consumed via LDS.128.
__global__ void __launch_bounds__(64, 1) apply_kernel(
    const float* __restrict__ x,
    const float* __restrict__ bias,
    float* __restrict__ out)
{
    __shared__ __align__(128) char sbuf[3][CHUNK_B];   // 41472 B
    __shared__ __align__(8) unsigned long long mbar[3];

    const int tid  = threadIdx.x;
    const int lane = tid & 31;
    const int row  = blockIdx.x * 2 + (tid >> 5);

    if (tid == 0) {
        mbar_init(s2u(&mbar[0]), 1);
        mbar_init(s2u(&mbar[1]), 1);
        mbar_init(s2u(&mbar[2]), 1);
    }

    // Load row, pack P[k] = (v_k, v_{k+8}); lane owns wires [16L, 16L+15]
    ull P[8];
    {
        float v[16];
        const float4* xr = reinterpret_cast<const float4*>(x + (size_t)row * N_WIRES) + lane * 4;
        #pragma unroll
        for (int j = 0; j < 4; ++j) {
            float4 f = xr[j];
            v[4*j+0] = f.x; v[4*j+1] = f.y; v[4*j+2] = f.z; v[4*j+3] = f.w;
        }
        #pragma unroll
        for (int k = 0; k < 8; ++k) P[k] = pk(v[k], v[k + 8]);
    }

    __syncthreads();    // mbar inits visible

    // prologue: issue chunks 0,1,2
    if (tid == 0) {
        #pragma unroll
        for (int pc = 0; pc < 3; ++pc) {
            unsigned mb = s2u(&mbar[pc]);
            mbar_expect_tx(mb, CHUNK_B);
            bulk_g2s(s2u(&sbuf[pc][0]), g_tab + (size_t)pc * CHUNK_B, CHUNK_B, mb);
        }
    }

    int rb = 0;           // buffer holding chunk c (rb == c % 3)
    #pragma unroll 1
    for (int c = 0; c < NCHUNK; ++c) {
        mbar_wait(s2u(&mbar[rb]), (unsigned)((c / 3) & 1));

        const char* cb = sbuf[rb];
        #pragma unroll
        for (int s = 0; s < CHUNK_L / 2; ++s) {
            const char* le = cb + (2 * s) * LAYER_B;
            const char* lo = le + LAYER_B;
            double2 E0 = *reinterpret_cast<const double2*>(le +    0 + lane * 16);
            double2 E1 = *reinterpret_cast<const double2*>(le +  512 + lane * 16);
            double2 E2 = *reinterpret_cast<const double2*>(le + 1024 + lane * 16);
            double2 E3 = *reinterpret_cast<const double2*>(le + 1536 + lane * 16);
            double2 O0 = *reinterpret_cast<const double2*>(lo +    0 + lane * 16);
            double2 O1 = *reinterpret_cast<const double2*>(lo +  512 + lane * 16);
            double2 O2 = *reinterpret_cast<const double2*>(lo + 1024 + lane * 16);
            double2 O3 = *reinterpret_cast<const double2*>(lo + 1536 + lane * 16);
            float2  LF = *reinterpret_cast<const float2*>(lo + LEFT_OFF + lane * 8);

            // ---- even layer ----
            rotp(P[0], P[1], E0);
            rotp(P[2], P[3], E1);
            rotp(P[4], P[5], E2);
            rotp(P[6], P[7], E3);
            // ---- odd layer ----
            float v16  = __shfl_down_sync(0xffffffffu, lo_f(P[0]), 1); // right nbr v0
            float lv15 = __shfl_up_sync  (0xffffffffu, hi_f(P[7]), 1); // left  nbr v15
            rotp(P[1], P[2], O0);
            rotp(P[3], P[4], O1);
            rotp(P[5], P[6], O2);
            ull Q = pk(hi_f(P[0]), v16);          // (v8, v16)
            rotp(P[7], Q, O3);                    // boundary: (v7,v15) x (v8,v16)
            // left gate updates v0 redundantly; lane 0 identity
            float nv0 = fmaf(LF.x, lo_f(P[0]), -(LF.y * lv15));
            P[0] = pk(nv0, lo_f(Q));              // (new v0, new v8)
        }

        __syncthreads();   // both warps done reading buffer rb
        if (tid == 0 && c + 3 < NCHUNK) {
            fence_async_shared();
            unsigned mb = s2u(&mbar[rb]);
            mbar_expect_tx(mb, CHUNK_B);
            bulk_g2s(s2u(&sbuf[rb][0]), g_tab + (size_t)(c + 3) * CHUNK_B, CHUNK_B, mb);
        }

        rb = (rb == 2) ? 0 : rb + 1;
    }

    // store + bias: wires 16L+k (lo halves), 16L+8+k (hi halves)
    {
        const float4* bb   = reinterpret_cast<const float4*>(bias) + lane * 4;
        float4*       outr = reinterpret_cast<float4*>(out + (size_t)row * N_WIRES) + lane * 4;
        float4 b0 = bb[0], b1 = bb[1], b2 = bb[2], b3 = bb[3];
        float4 o0, o1, o2, o3;
        o0.x = lo_f(P[0]) + b0.x; o0.y = lo_f(P[1]) + b0.y;
        o0.z = lo_f(P[2]) + b0.z; o0.w = lo_f(P[3]) + b0.w;
        o1.x = lo_f(P[4]) + b1.x; o1.y = lo_f(P[5]) + b1.y;
        o1.z = lo_f(P[6]) + b1.z; o1.w = lo_f(P[7]) + b1.w;
        o2.x = hi_f(P[0]) + b2.x; o2.y = hi_f(P[1]) + b2.y;
        o2.z = hi_f(P[2]) + b2.z; o2.w = hi_f(P[3]) + b2.w;
        o3.x = hi_f(P[4]) + b3.x; o3.y = hi_f(P[5]) + b3.y;
        o3.z = hi_f(P[6]) + b3.z; o3.w = hi_f(P[7]) + b3.w;
        outr[0] = o0; outr[1] = o1; outr[2] = o2; outr[3] = o3;
    }
}

extern "C" void kernel_launch(void* const* d_in, const int* in_sizes, int n_in,
                              void* d_out, int out_size) {
    const float* x      = (const float*)d_in[0];
    const float* thetas = (const float*)d_in[1];
    const float* bias   = (const float*)d_in[2];
    float* out = (float*)d_out;

    build_cs_kernel<<<T_PAD, 128>>>(thetas);

    int B = in_sizes[0] / N_WIRES;   // 256
    apply_kernel<<<B / 2, 64>>>(x, bias, out);
}